// round 1
// baseline (speedup 1.0000x reference)
#include <cuda_runtime.h>
#include <cuda_bf16.h>
#include <float.h>

// Problem constants
#define BB    8
#define NN    2048
#define KK    16
#define KD    32      // K*D
#define MM    256     // K*K
#define CIN   64
#define CL    64      // C_LIFT
#define COUT  128
#define BN_EPS 1e-3f
#define LARGE_DIST 1e9f

// fused kernel tiling
#define PPB   8       // points per block
#define THR   256     // threads per block

// scratch: neighbor indices [B,N,K]
__device__ int g_idx[BB * NN * KK];

// ---------------------------------------------------------------------------
// Kernel 1: KNN. One thread per query point; batch xyz staged in shared.
// Strict '<' insertion reproduces jax.lax.top_k tie-breaking (lowest index
// first among equal distances), including the all-1e9 masked case -> idx 0..15.
// ---------------------------------------------------------------------------
__global__ __launch_bounds__(128)
void knn_kernel(const float* __restrict__ xyz, int* __restrict__ idx_out) {
    __shared__ float4 spts[NN];   // x,y,z,mask  (32KB)

    const int tid = threadIdx.x;
    const int g   = blockIdx.x * 128 + tid;   // global point id
    const int b   = g >> 11;                  // /2048
    const int n   = g & (NN - 1);

    // load this batch's points into shared
    for (int j = tid; j < NN; j += 128) {
        const float* p = xyz + ((size_t)b * NN + j) * 3;
        float x = p[0], y = p[1], z = p[2];
        float m = (x != 0.0f || y != 0.0f || z != 0.0f) ? 1.0f : 0.0f;
        spts[j] = make_float4(x, y, z, m);
    }
    __syncthreads();

    float4 q = spts[n];
    bool qm = (q.w != 0.0f);

    float bd[KK];
    int   bi[KK];
#pragma unroll
    for (int t = 0; t < KK; t++) { bd[t] = FLT_MAX; bi[t] = 0; }

    for (int j = 0; j < NN; j++) {
        float4 pj = spts[j];
        float dx = q.x - pj.x;
        float dy = q.y - pj.y;
        float dz = q.z - pj.z;
        float d  = dx * dx + dy * dy + dz * dz;
        bool valid = qm && (pj.w != 0.0f);
        d = valid ? d : LARGE_DIST;
        if (d < bd[KK - 1]) {
            bd[KK - 1] = d; bi[KK - 1] = j;
#pragma unroll
            for (int t = KK - 1; t > 0; --t) {
                if (bd[t] < bd[t - 1]) {
                    float td = bd[t]; bd[t] = bd[t - 1]; bd[t - 1] = td;
                    int   ti = bi[t]; bi[t] = bi[t - 1]; bi[t - 1] = ti;
                }
            }
        }
    }

#pragma unroll
    for (int t = 0; t < KK; t++) idx_out[(size_t)g * KK + t] = bi[t];
}

// ---------------------------------------------------------------------------
// Kernel 2: fused per-point pipeline, PPB points per block.
// Stages: gather -> h (rel@w1, relu, BN) -> X (h@w2 + b2) ->
//         lifted (feat@wl, BN, relu, mask) -> transformed (X@lifted) ->
//         out (transformed . wf, BN, relu, mask)
// ---------------------------------------------------------------------------
__global__ __launch_bounds__(THR)
void fused_kernel(
    const float* __restrict__ xyz,     const float* __restrict__ feat,
    const float* __restrict__ w1,      const float* __restrict__ b1,
    const float* __restrict__ gamma1,  const float* __restrict__ beta1,
    const float* __restrict__ mean1,   const float* __restrict__ var1,
    const float* __restrict__ w2,      const float* __restrict__ b2,
    const float* __restrict__ wl,
    const float* __restrict__ gamma_l, const float* __restrict__ beta_l,
    const float* __restrict__ mean_l,  const float* __restrict__ var_l,
    const float* __restrict__ wf,
    const float* __restrict__ gamma_f, const float* __restrict__ beta_f,
    const float* __restrict__ mean_f,  const float* __restrict__ var_f,
    const int*   __restrict__ nbr_idx,
    float* __restrict__ out)
{
    extern __shared__ float sm[];
    float* s_rel   = sm;                    // PPB*16*3        = 384
    float* s_nmask = s_rel + PPB * 48;      // PPB*16          = 128
    float* s_qmask = s_nmask + PPB * 16;    // PPB             = 8
    int*   s_idx   = (int*)(s_qmask + PPB); // PPB*16          = 128
    float* s_h     = (float*)(s_idx + PPB * 16); // PPB*512    = 4096
    float* s_X     = s_h + PPB * 512;       // PPB*256         = 2048
    float* s_feat  = s_X + PPB * 256;       // PPB*16*64       = 8192
    float* s_lift  = s_feat + PPB * 1024;   // PPB*16*64       = 8192
    float* s_red   = s_lift + PPB * 1024;   // 256
    // total 23432 floats = 93728 bytes

    const int tid = threadIdx.x;
    const int g0  = blockIdx.x * PPB;       // first point of this block
    const int b   = g0 >> 11;               // all PPB points share batch

    // ---- Stage A: neighbor idx, rel_xyz, masks ----
    if (tid < PPB * KK) {
        const int p = tid >> 4;
        const int k = tid & 15;
        const int g = g0 + p;
        const int n = g & (NN - 1);
        const int nbr = nbr_idx[(size_t)g * KK + k];
        const float* pq = xyz + ((size_t)b * NN + n) * 3;
        const float* pn = xyz + ((size_t)b * NN + nbr) * 3;
        float qx = pq[0], qy = pq[1], qz = pq[2];
        float px = pn[0], py = pn[1], pz = pn[2];
        float nm = (px != 0.0f || py != 0.0f || pz != 0.0f) ? 1.0f : 0.0f;
        s_rel[(p * 16 + k) * 3 + 0] = nm * (px - qx);
        s_rel[(p * 16 + k) * 3 + 1] = nm * (py - qy);
        s_rel[(p * 16 + k) * 3 + 2] = nm * (pz - qz);
        s_nmask[p * 16 + k] = nm;
        s_idx[p * 16 + k]   = nbr;
        if (k == 0)
            s_qmask[p] = (qx != 0.0f || qy != 0.0f || qz != 0.0f) ? 1.0f : 0.0f;
    }
    __syncthreads();

    // ---- Stage B: gather neighbor features into shared ----
    for (int e = tid; e < PPB * KK * CIN; e += THR) {
        const int c = e & 63;
        const int k = (e >> 6) & 15;
        const int p = e >> 10;
        const int nbr = s_idx[p * 16 + k];
        s_feat[p * 1024 + k * 64 + c] =
            feat[((size_t)b * NN + nbr) * CIN + c];
    }

    // ---- Stage C: h = BN(relu(rel@w1 + b1))  [p][k][d] -> s_h[p][512] ----
    for (int e = tid; e < PPB * 512; e += THR) {
        const int p = e >> 9;
        const int j = e & 511;        // j = k*32 + d
        const int k = j >> 5;
        const int d = j & 31;
        const float* r = s_rel + (p * 16 + k) * 3;
        float v = r[0] * w1[d] + r[1] * w1[32 + d] + r[2] * w1[64 + d] + b1[d];
        v = fmaxf(v, 0.0f);
        float sc = gamma1[d] * rsqrtf(var1[d] + BN_EPS);
        v = (v - mean1[d]) * sc + beta1[d];
        s_h[e] = v;
    }
    __syncthreads();

    // ---- Stage D: X[m] = sum_j h[j] * w2[j][m] + b2[m]  (m = tid) ----
    {
        float acc[PPB];
#pragma unroll
        for (int p = 0; p < PPB; p++) acc[p] = 0.0f;
#pragma unroll 4
        for (int j = 0; j < 512; j++) {
            float wv = w2[(size_t)j * MM + tid];
#pragma unroll
            for (int p = 0; p < PPB; p++)
                acc[p] = fmaf(s_h[p * 512 + j], wv, acc[p]);
        }
        float bias = b2[tid];
#pragma unroll
        for (int p = 0; p < PPB; p++) s_X[p * 256 + tid] = acc[p] + bias;
    }

    // ---- Stage E: lifted = mask * relu(BN(feat@wl))  [p][k][l] ----
    {
        const int l  = tid & 63;
        const int kk = tid >> 6;     // 0..3
        float scl = gamma_l[l] * rsqrtf(var_l[l] + BN_EPS);
        float shl = beta_l[l] - mean_l[l] * scl;
#pragma unroll
        for (int kq = 0; kq < 4; kq++) {
            const int k = kk * 4 + kq;
            for (int p = 0; p < PPB; p++) {
                const float* fr = s_feat + p * 1024 + k * 64;
                float acc = 0.0f;
#pragma unroll 8
                for (int c = 0; c < 64; c++)
                    acc = fmaf(fr[c], wl[c * 64 + l], acc);
                float v = acc * scl + shl;
                v = fmaxf(v, 0.0f) * s_nmask[p * 16 + k];
                s_lift[p * 1024 + k * 64 + l] = v;
            }
        }
    }
    __syncthreads();

    // ---- Stage F: transformed[i][l] = sum_j X[i][j]*lifted[j][l] ----
    {
        const int l  = tid & 63;
        const int kk = tid >> 6;
        float tr[PPB][4];
#pragma unroll
        for (int kq = 0; kq < 4; kq++) {
            const int i = kk * 4 + kq;
#pragma unroll
            for (int p = 0; p < PPB; p++) {
                float acc = 0.0f;
#pragma unroll
                for (int j = 0; j < 16; j++)
                    acc = fmaf(s_X[p * 256 + i * 16 + j],
                               s_lift[p * 1024 + j * 64 + l], acc);
                tr[p][kq] = acc;
            }
        }
        __syncthreads();
#pragma unroll
        for (int kq = 0; kq < 4; kq++) {
            const int i = kk * 4 + kq;
#pragma unroll
            for (int p = 0; p < PPB; p++)
                s_lift[p * 1024 + i * 64 + l] = tr[p][kq];
        }
    }
    __syncthreads();

    // ---- Stage G: out[o] = relu(BN(sum_{k,l} transformed[k][l]*wf[k][l][o])) ----
    {
        const int o    = tid & 127;
        const int half = tid >> 7;   // k range split
        float scf = gamma_f[o] * rsqrtf(var_f[o] + BN_EPS);
        float shf = beta_f[o] - mean_f[o] * scf;

        float acc[PPB];
#pragma unroll
        for (int p = 0; p < PPB; p++) acc[p] = 0.0f;

        for (int k = half * 8; k < half * 8 + 8; k++) {
#pragma unroll 4
            for (int l = 0; l < 64; l++) {
                float wv = wf[((size_t)(k * 64 + l)) * COUT + o];
#pragma unroll
                for (int p = 0; p < PPB; p++)
                    acc[p] = fmaf(s_lift[p * 1024 + k * 64 + l], wv, acc[p]);
            }
        }

        for (int p = 0; p < PPB; p++) {
            s_red[tid] = acc[p];
            __syncthreads();
            if (tid < 128) {
                float v = s_red[tid] + s_red[tid + 128];
                v = v * scf + shf;
                v = fmaxf(v, 0.0f) * s_qmask[p];
                out[(size_t)(g0 + p) * COUT + tid] = v;
            }
            __syncthreads();
        }
    }
}

// ---------------------------------------------------------------------------
extern "C" void kernel_launch(void* const* d_in, const int* in_sizes, int n_in,
                              void* d_out, int out_size) {
    const float* xyz     = (const float*)d_in[0];
    const float* feat    = (const float*)d_in[1];
    const float* w1      = (const float*)d_in[2];
    const float* b1      = (const float*)d_in[3];
    const float* gamma1  = (const float*)d_in[4];
    const float* beta1   = (const float*)d_in[5];
    const float* mean1   = (const float*)d_in[6];
    const float* var1    = (const float*)d_in[7];
    const float* w2      = (const float*)d_in[8];
    const float* b2      = (const float*)d_in[9];
    const float* wl      = (const float*)d_in[10];
    const float* gamma_l = (const float*)d_in[11];
    const float* beta_l  = (const float*)d_in[12];
    const float* mean_l  = (const float*)d_in[13];
    const float* var_l   = (const float*)d_in[14];
    const float* wf      = (const float*)d_in[15];
    const float* gamma_f = (const float*)d_in[16];
    const float* beta_f  = (const float*)d_in[17];
    const float* mean_f  = (const float*)d_in[18];
    const float* var_f   = (const float*)d_in[19];
    float* out = (float*)d_out;

    int* idx_ptr;
    cudaGetSymbolAddress((void**)&idx_ptr, g_idx);

    // KNN: 128 threads/block, 128 points each
    knn_kernel<<<(BB * NN) / 128, 128>>>(xyz, idx_ptr);

    // fused pipeline
    const int smem_bytes = 23432 * 4;   // 93728
    cudaFuncSetAttribute(fused_kernel,
                         cudaFuncAttributeMaxDynamicSharedMemorySize,
                         smem_bytes);
    fused_kernel<<<(BB * NN) / PPB, THR, smem_bytes>>>(
        xyz, feat, w1, b1, gamma1, beta1, mean1, var1, w2, b2,
        wl, gamma_l, beta_l, mean_l, var_l,
        wf, gamma_f, beta_f, mean_f, var_f,
        idx_ptr, out);
}

// round 2
// speedup vs baseline: 1.4316x; 1.4316x over previous
#include <cuda_runtime.h>
#include <float.h>

#define BB    8
#define NN    2048
#define KK    16
#define CIN   64
#define COUT  128
#define BN_EPS 1e-3f
#define LARGE_DIST 1e9f

#define PPB   8
#define THR   256
#define SPLIT 8
#define CAND  (NN / SPLIT)   // 256

// scratch
__device__ float g_pd[BB * NN * SPLIT * KK];
__device__ int   g_pi[BB * NN * SPLIT * KK];
__device__ int   g_idx[BB * NN * KK];

// ---- packed fp32x2 helpers ------------------------------------------------
__device__ __forceinline__ unsigned long long pack2(float lo, float hi) {
    unsigned long long r;
    asm("mov.b64 %0, {%1, %2};" : "=l"(r) : "f"(lo), "f"(hi));
    return r;
}
__device__ __forceinline__ float2 unpack2(unsigned long long v) {
    float2 r;
    asm("mov.b64 {%0, %1}, %2;" : "=f"(r.x), "=f"(r.y) : "l"(v));
    return r;
}
__device__ __forceinline__ void ffma2(unsigned long long& a,
                                      unsigned long long x,
                                      unsigned long long y) {
    asm("fma.rn.f32x2 %0, %1, %2, %0;" : "+l"(a) : "l"(x), "l"(y));
}

// ---------------------------------------------------------------------------
// KNN part 1: each block scans a 256-candidate slice for 128 queries.
// Strict '<' insertion preserves jax.lax.top_k tie order (lower index wins).
// ---------------------------------------------------------------------------
__global__ __launch_bounds__(128)
void knn_part(const float* __restrict__ xyz,
              float* __restrict__ pd, int* __restrict__ pi) {
    __shared__ float4 spts[NN];
    const int tid = threadIdx.x;
    const int qg  = blockIdx.x >> 3;
    const int sp  = blockIdx.x & 7;
    const int g   = qg * 128 + tid;
    const int b   = g >> 11;
    const int n   = g & (NN - 1);

    for (int j = tid; j < NN; j += 128) {
        const float* p = xyz + ((size_t)b * NN + j) * 3;
        float x = p[0], y = p[1], z = p[2];
        float m = (x != 0.0f || y != 0.0f || z != 0.0f) ? 1.0f : 0.0f;
        spts[j] = make_float4(x, y, z, m);
    }
    __syncthreads();

    float4 q = spts[n];
    bool qm = (q.w != 0.0f);

    float bd[KK]; int bi[KK];
#pragma unroll
    for (int t = 0; t < KK; t++) { bd[t] = FLT_MAX; bi[t] = 0; }

    const int j0 = sp * CAND;
#pragma unroll 4
    for (int jj = 0; jj < CAND; jj++) {
        int j = j0 + jj;
        float4 pj = spts[j];
        float dx = q.x - pj.x, dy = q.y - pj.y, dz = q.z - pj.z;
        float d = dx * dx + dy * dy + dz * dz;
        d = (qm && pj.w != 0.0f) ? d : LARGE_DIST;
        if (d < bd[KK - 1]) {
            bd[KK - 1] = d; bi[KK - 1] = j;
#pragma unroll
            for (int t = KK - 1; t > 0; --t) {
                if (bd[t] < bd[t - 1]) {
                    float td = bd[t]; bd[t] = bd[t - 1]; bd[t - 1] = td;
                    int   ti = bi[t]; bi[t] = bi[t - 1]; bi[t - 1] = ti;
                }
            }
        }
    }
    float* po = pd + ((size_t)g * SPLIT + sp) * KK;
    int*   io = pi + ((size_t)g * SPLIT + sp) * KK;
#pragma unroll
    for (int t = 0; t < KK; t++) { po[t] = bd[t]; io[t] = bi[t]; }
}

// ---------------------------------------------------------------------------
// KNN part 2: merge SPLIT partial top-16 lists per query.
// Quarters processed in ascending j order -> tie order preserved.
// ---------------------------------------------------------------------------
__global__ __launch_bounds__(128)
void knn_merge(const float* __restrict__ pd, const int* __restrict__ pi,
               int* __restrict__ idx_out) {
    const int g = blockIdx.x * 128 + threadIdx.x;
    float bd[KK]; int bi[KK];
#pragma unroll
    for (int t = 0; t < KK; t++) { bd[t] = FLT_MAX; bi[t] = 0; }

    const float* pp = pd + (size_t)g * SPLIT * KK;
    const int*   ii = pi + (size_t)g * SPLIT * KK;
    for (int c = 0; c < SPLIT * KK; c++) {
        float d = pp[c]; int i = ii[c];
        if (d < bd[KK - 1]) {
            bd[KK - 1] = d; bi[KK - 1] = i;
#pragma unroll
            for (int t = KK - 1; t > 0; --t) {
                if (bd[t] < bd[t - 1]) {
                    float td = bd[t]; bd[t] = bd[t - 1]; bd[t - 1] = td;
                    int   ti = bi[t]; bi[t] = bi[t - 1]; bi[t - 1] = ti;
                }
            }
        }
    }
#pragma unroll
    for (int t = 0; t < KK; t++) idx_out[(size_t)g * KK + t] = bi[t];
}

// ---------------------------------------------------------------------------
// Fused per-point pipeline, PPB=8 points/block, transposed [*][p] layouts,
// packed f32x2 FMAs, smem overlays (51.7KB -> 4 blocks/SM).
// ---------------------------------------------------------------------------
__global__ __launch_bounds__(THR, 4)
void fused_kernel(
    const float* __restrict__ xyz,     const float* __restrict__ feat,
    const float* __restrict__ w1,      const float* __restrict__ b1,
    const float* __restrict__ gamma1,  const float* __restrict__ beta1,
    const float* __restrict__ mean1,   const float* __restrict__ var1,
    const float* __restrict__ w2,      const float* __restrict__ b2,
    const float* __restrict__ wl,
    const float* __restrict__ gamma_l, const float* __restrict__ beta_l,
    const float* __restrict__ mean_l,  const float* __restrict__ var_l,
    const float* __restrict__ wf,
    const float* __restrict__ gamma_f, const float* __restrict__ beta_f,
    const float* __restrict__ mean_f,  const float* __restrict__ var_f,
    const int*   __restrict__ nbr_idx,
    float* __restrict__ out)
{
    extern __shared__ float sm[];
    float* s_hx    = sm;            // [4096] hT[j*8+p]; later XT[m*8+p] (0..2047) + red (2048..4095)
    float* s_fl    = sm + 4096;     // [8192] featT[(k*64+c)*8+p] -> liftT/tr[(k*64+l)*8+p]
    float* s_rel   = sm + 12288;    // [384]
    float* s_nmask = sm + 12672;    // [128]
    float* s_qmask = sm + 12800;    // [8]
    int*   s_idx   = (int*)(sm + 12808); // [128]
    // total 12936 floats = 51744 bytes

    const int tid = threadIdx.x;
    const int g0  = blockIdx.x * PPB;
    const int b   = g0 >> 11;

    // ---- Stage A: rel_xyz, masks, neighbor idx ----
    if (tid < PPB * KK) {
        const int p = tid >> 4;
        const int k = tid & 15;
        const int g = g0 + p;
        const int n = g & (NN - 1);
        const int nbr = nbr_idx[(size_t)g * KK + k];
        const float* pq = xyz + ((size_t)b * NN + n) * 3;
        const float* pn = xyz + ((size_t)b * NN + nbr) * 3;
        float qx = pq[0], qy = pq[1], qz = pq[2];
        float px = pn[0], py = pn[1], pz = pn[2];
        float nm = (px != 0.0f || py != 0.0f || pz != 0.0f) ? 1.0f : 0.0f;
        s_rel[(p * 16 + k) * 3 + 0] = nm * (px - qx);
        s_rel[(p * 16 + k) * 3 + 1] = nm * (py - qy);
        s_rel[(p * 16 + k) * 3 + 2] = nm * (pz - qz);
        s_nmask[p * 16 + k] = nm;
        s_idx[p * 16 + k]   = nbr;
        if (k == 0)
            s_qmask[p] = (qx != 0.0f || qy != 0.0f || qz != 0.0f) ? 1.0f : 0.0f;
    }
    __syncthreads();

    // ---- Stage B: gather neighbor features -> featT[(k*64+c)*8+p] ----
    for (int e = tid; e < PPB * KK * CIN / 4; e += THR) {
        int c4 = (e & 15) * 4;
        int k  = (e >> 4) & 15;
        int p  = e >> 8;
        int nbr = s_idx[p * 16 + k];
        float4 f = *(const float4*)(feat + ((size_t)b * NN + nbr) * CIN + c4);
        s_fl[(k * 64 + c4 + 0) * 8 + p] = f.x;
        s_fl[(k * 64 + c4 + 1) * 8 + p] = f.y;
        s_fl[(k * 64 + c4 + 2) * 8 + p] = f.z;
        s_fl[(k * 64 + c4 + 3) * 8 + p] = f.w;
    }

    // ---- Stage C: hT[j*8+p] = BN(relu(rel@w1+b1)) ----
    for (int e = tid; e < PPB * 512; e += THR) {
        int p = e & 7;
        int j = e >> 3;
        int k = j >> 5;
        int d = j & 31;
        const float* r = s_rel + (p * 16 + k) * 3;
        float v = r[0] * w1[d] + r[1] * w1[32 + d] + r[2] * w1[64 + d] + b1[d];
        v = fmaxf(v, 0.0f);
        float sc = gamma1[d] * rsqrtf(var1[d] + BN_EPS);
        v = (v - mean1[d]) * sc + beta1[d];
        s_hx[e] = v;                       // e == j*8+p
    }
    __syncthreads();

    // ---- Stage D: X[m][p] = sum_j hT[j][p] * w2[j][m] + b2[m] ----
    {
        unsigned long long acc[4] = {0, 0, 0, 0};
        const float* w2c = w2 + tid;
#pragma unroll 4
        for (int j = 0; j < 512; j++) {
            float wv = w2c[(size_t)j * 256];
            unsigned long long wv2 = pack2(wv, wv);
            const ulonglong2* hp = (const ulonglong2*)(s_hx + j * 8);
            ulonglong2 hA = hp[0];
            ulonglong2 hB = hp[1];
            ffma2(acc[0], hA.x, wv2);
            ffma2(acc[1], hA.y, wv2);
            ffma2(acc[2], hB.x, wv2);
            ffma2(acc[3], hB.y, wv2);
        }
        __syncthreads();                   // hT dead -> overlay XT
        float bias = b2[tid];
        float* xo = s_hx + tid * 8;
#pragma unroll
        for (int q = 0; q < 4; q++) {
            float2 a = unpack2(acc[q]);
            xo[2 * q]     = a.x + bias;
            xo[2 * q + 1] = a.y + bias;
        }
    }

    // ---- Stage E: liftT = mask*relu(BN(featT@wl)), overlay onto featT ----
    {
        const int l     = tid & 63;
        const int kbase = tid >> 6;
        float scl = gamma_l[l] * rsqrtf(var_l[l] + BN_EPS);
        float shl = beta_l[l] - mean_l[l] * scl;
        for (int t = 0; t < 4; t++) {
            const int k = t * 4 + kbase;
            unsigned long long ea[4] = {0, 0, 0, 0};
            const float* wlc = wl + l;
            const ulonglong2* fp = (const ulonglong2*)(s_fl + k * 64 * 8);
#pragma unroll 4
            for (int c = 0; c < 64; c++) {
                float wv = wlc[c * 64];
                unsigned long long wv2 = pack2(wv, wv);
                ulonglong2 fA = fp[2 * c];
                ulonglong2 fB = fp[2 * c + 1];
                ffma2(ea[0], fA.x, wv2);
                ffma2(ea[1], fA.y, wv2);
                ffma2(ea[2], fB.x, wv2);
                ffma2(ea[3], fB.y, wv2);
            }
            float v[8];
#pragma unroll
            for (int q = 0; q < 4; q++) {
                float2 a = unpack2(ea[q]);
                v[2 * q] = a.x; v[2 * q + 1] = a.y;
            }
#pragma unroll
            for (int p = 0; p < 8; p++) {
                float x = v[p] * scl + shl;
                v[p] = fmaxf(x, 0.0f) * s_nmask[p * 16 + k];
            }
            __syncthreads();   // this pass's featT rows fully read by all
            float4* lo = (float4*)(s_fl + (k * 64 + l) * 8);
            lo[0] = make_float4(v[0], v[1], v[2], v[3]);
            lo[1] = make_float4(v[4], v[5], v[6], v[7]);
        }
    }
    __syncthreads();

    // ---- Stage F: tr[i][l][p] = sum_j X[i*16+j][p] * liftT[j][l][p] ----
    {
        const int l    = tid & 63;
        const int igrp = tid >> 6;
        unsigned long long fa[4][4];
#pragma unroll
        for (int t = 0; t < 4; t++) {
            const int i = t * 4 + igrp;
#pragma unroll
            for (int q = 0; q < 4; q++) fa[t][q] = 0;
#pragma unroll
            for (int j = 0; j < 16; j++) {
                const ulonglong2* xp = (const ulonglong2*)(s_hx + (i * 16 + j) * 8);
                const ulonglong2* lp = (const ulonglong2*)(s_fl + (j * 64 + l) * 8);
                ulonglong2 xA = xp[0], xB = xp[1];
                ulonglong2 lA = lp[0], lB = lp[1];
                ffma2(fa[t][0], xA.x, lA.x);
                ffma2(fa[t][1], xA.y, lA.y);
                ffma2(fa[t][2], xB.x, lB.x);
                ffma2(fa[t][3], xB.y, lB.y);
            }
        }
        __syncthreads();                   // liftT dead -> overlay tr
#pragma unroll
        for (int t = 0; t < 4; t++) {
            const int i = t * 4 + igrp;
            ulonglong2* o = (ulonglong2*)(s_fl + (i * 64 + l) * 8);
            o[0] = make_ulonglong2(fa[t][0], fa[t][1]);
            o[1] = make_ulonglong2(fa[t][2], fa[t][3]);
        }
    }
    __syncthreads();

    // ---- Stage G: out[p][o] = relu(BN(sum_kl tr[kl][p]*wf[kl][o])) ----
    {
        const int o    = tid & 127;
        const int half = tid >> 7;
        unsigned long long ga[4] = {0, 0, 0, 0};
        const float* wfc = wf + o;
        const int kl0 = half * 512;
#pragma unroll 4
        for (int klr = 0; klr < 512; klr++) {
            int kl = kl0 + klr;
            float wv = wfc[(size_t)kl * 128];
            unsigned long long wv2 = pack2(wv, wv);
            const ulonglong2* tp = (const ulonglong2*)(s_fl + kl * 8);
            ulonglong2 tA = tp[0], tB = tp[1];
            ffma2(ga[0], tA.x, wv2);
            ffma2(ga[1], tA.y, wv2);
            ffma2(ga[2], tB.x, wv2);
            ffma2(ga[3], tB.y, wv2);
        }
        float* rh = s_hx + 2048 + half * 1024;   // hT upper half: dead
#pragma unroll
        for (int q = 0; q < 4; q++) {
            float2 a = unpack2(ga[q]);
            rh[(2 * q) * 128 + o]     = a.x;
            rh[(2 * q + 1) * 128 + o] = a.y;
        }
    }
    __syncthreads();

    // ---- final reduce + BN + relu + mask + store ----
    for (int e = tid; e < PPB * COUT; e += THR) {
        int p  = e >> 7;
        int oc = e & 127;
        float v = s_hx[2048 + p * 128 + oc] + s_hx[2048 + 1024 + p * 128 + oc];
        float scf = gamma_f[oc] * rsqrtf(var_f[oc] + BN_EPS);
        float shf = beta_f[oc] - mean_f[oc] * scf;
        v = v * scf + shf;
        v = fmaxf(v, 0.0f) * s_qmask[p];
        out[(size_t)(g0 + p) * COUT + oc] = v;
    }
}

// ---------------------------------------------------------------------------
extern "C" void kernel_launch(void* const* d_in, const int* in_sizes, int n_in,
                              void* d_out, int out_size) {
    const float* xyz     = (const float*)d_in[0];
    const float* feat    = (const float*)d_in[1];
    const float* w1      = (const float*)d_in[2];
    const float* b1      = (const float*)d_in[3];
    const float* gamma1  = (const float*)d_in[4];
    const float* beta1   = (const float*)d_in[5];
    const float* mean1   = (const float*)d_in[6];
    const float* var1    = (const float*)d_in[7];
    const float* w2      = (const float*)d_in[8];
    const float* b2      = (const float*)d_in[9];
    const float* wl      = (const float*)d_in[10];
    const float* gamma_l = (const float*)d_in[11];
    const float* beta_l  = (const float*)d_in[12];
    const float* mean_l  = (const float*)d_in[13];
    const float* var_l   = (const float*)d_in[14];
    const float* wf      = (const float*)d_in[15];
    const float* gamma_f = (const float*)d_in[16];
    const float* beta_f  = (const float*)d_in[17];
    const float* mean_f  = (const float*)d_in[18];
    const float* var_f   = (const float*)d_in[19];
    float* out = (float*)d_out;

    float* pd_ptr;  int* pi_ptr;  int* idx_ptr;
    cudaGetSymbolAddress((void**)&pd_ptr, g_pd);
    cudaGetSymbolAddress((void**)&pi_ptr, g_pi);
    cudaGetSymbolAddress((void**)&idx_ptr, g_idx);

    knn_part<<<(BB * NN / 128) * SPLIT, 128>>>(xyz, pd_ptr, pi_ptr);
    knn_merge<<<BB * NN / 128, 128>>>(pd_ptr, pi_ptr, idx_ptr);

    const int smem_bytes = 12936 * 4;   // 51744
    cudaFuncSetAttribute(fused_kernel,
                         cudaFuncAttributeMaxDynamicSharedMemorySize,
                         smem_bytes);
    fused_kernel<<<(BB * NN) / PPB, THR, smem_bytes>>>(
        xyz, feat, w1, b1, gamma1, beta1, mean1, var1, w2, b2,
        wl, gamma_l, beta_l, mean_l, var_l,
        wf, gamma_f, beta_f, mean_f, var_f,
        idx_ptr, out);
}

// round 3
// speedup vs baseline: 1.5840x; 1.1065x over previous
#include <cuda_runtime.h>
#include <float.h>

#define BB    8
#define NN    2048
#define KK    16
#define CIN   64
#define COUT  128
#define BN_EPS 1e-3f
#define LARGE_DIST 1e9f

#define SPLIT 8
#define CAND  (NN / SPLIT)   // 256
#define NPTS  (BB * NN)      // 16384

// ---- global scratch -------------------------------------------------------
__device__ float g_pd[NPTS * SPLIT * KK];
__device__ int   g_pi[NPTS * SPLIT * KK];
__device__ int   g_idx[NPTS * KK];
__device__ float g_h[(size_t)NPTS * 512];
__device__ float g_X[(size_t)NPTS * 256];
__device__ float g_lift[(size_t)NPTS * 16 * 64];
__device__ float g_tr[(size_t)NPTS * 1024];

// ---- packed fp32x2 helpers ------------------------------------------------
__device__ __forceinline__ unsigned long long pack2(float lo, float hi) {
    unsigned long long r;
    asm("mov.b64 %0, {%1, %2};" : "=l"(r) : "f"(lo), "f"(hi));
    return r;
}
__device__ __forceinline__ float2 unpack2(unsigned long long v) {
    float2 r;
    asm("mov.b64 {%0, %1}, %2;" : "=f"(r.x), "=f"(r.y) : "l"(v));
    return r;
}
__device__ __forceinline__ void ffma2(unsigned long long& a,
                                      unsigned long long x,
                                      unsigned long long y) {
    asm("fma.rn.f32x2 %0, %1, %2, %0;" : "+l"(a) : "l"(x), "l"(y));
}
__device__ __forceinline__ unsigned long long add2(unsigned long long x,
                                                   unsigned long long y) {
    unsigned long long r;
    asm("add.rn.f32x2 %0, %1, %2;" : "=l"(r) : "l"(x), "l"(y));
    return r;
}
__device__ __forceinline__ unsigned long long mul2(unsigned long long x,
                                                   unsigned long long y) {
    unsigned long long r;
    asm("mul.rn.f32x2 %0, %1, %2;" : "=l"(r) : "l"(x), "l"(y));
    return r;
}

// ---------------------------------------------------------------------------
// KNN part 1: f32x2 paired candidates. Strict '<' insertion keeps top_k tie
// order (lower index wins). Invalid points handled by +1e9 penalty (output-
// equivalent: invalid neighbors are masked downstream, invalid queries are
// masked at the end).
// ---------------------------------------------------------------------------
__device__ __forceinline__ void insert16(float* bd, int* bi, float d, int j) {
    bd[KK - 1] = d; bi[KK - 1] = j;
#pragma unroll
    for (int t = KK - 1; t > 0; --t) {
        if (bd[t] < bd[t - 1]) {
            float td = bd[t]; bd[t] = bd[t - 1]; bd[t - 1] = td;
            int   ti = bi[t]; bi[t] = bi[t - 1]; bi[t - 1] = ti;
        }
    }
}

__global__ __launch_bounds__(128)
void knn_part(const float* __restrict__ xyz,
              float* __restrict__ pd, int* __restrict__ pi) {
    __shared__ float s_nx[NN], s_ny[NN], s_nz[NN], s_pen[NN];
    const int tid = threadIdx.x;
    const int qg  = blockIdx.x >> 3;
    const int sp  = blockIdx.x & 7;
    const int g   = qg * 128 + tid;
    const int b   = g >> 11;
    const int n   = g & (NN - 1);

    for (int j = tid; j < NN; j += 128) {
        const float* p = xyz + ((size_t)b * NN + j) * 3;
        float x = p[0], y = p[1], z = p[2];
        bool v = (x != 0.0f || y != 0.0f || z != 0.0f);
        s_nx[j] = -x; s_ny[j] = -y; s_nz[j] = -z;
        s_pen[j] = v ? 0.0f : LARGE_DIST;
    }
    __syncthreads();

    const float* qp = xyz + ((size_t)b * NN + n) * 3;
    unsigned long long qx2 = pack2(qp[0], qp[0]);
    unsigned long long qy2 = pack2(qp[1], qp[1]);
    unsigned long long qz2 = pack2(qp[2], qp[2]);

    float bd[KK]; int bi[KK];
#pragma unroll
    for (int t = 0; t < KK; t++) { bd[t] = FLT_MAX; bi[t] = 0; }

    const unsigned long long* px2 = (const unsigned long long*)s_nx + sp * (CAND / 2);
    const unsigned long long* py2 = (const unsigned long long*)s_ny + sp * (CAND / 2);
    const unsigned long long* pz2 = (const unsigned long long*)s_nz + sp * (CAND / 2);
    const unsigned long long* pp2 = (const unsigned long long*)s_pen + sp * (CAND / 2);
    const int jbase = sp * CAND;

#pragma unroll 4
    for (int jj = 0; jj < CAND / 2; jj++) {
        unsigned long long dx2 = add2(qx2, px2[jj]);
        unsigned long long dy2 = add2(qy2, py2[jj]);
        unsigned long long dz2 = add2(qz2, pz2[jj]);
        unsigned long long d2  = mul2(dx2, dx2);
        ffma2(d2, dy2, dy2);
        ffma2(d2, dz2, dz2);
        d2 = add2(d2, pp2[jj]);
        float2 d = unpack2(d2);
        if (d.x < bd[KK - 1]) insert16(bd, bi, d.x, jbase + 2 * jj);
        if (d.y < bd[KK - 1]) insert16(bd, bi, d.y, jbase + 2 * jj + 1);
    }

    float* po = pd + ((size_t)g * SPLIT + sp) * KK;
    int*   io = pi + ((size_t)g * SPLIT + sp) * KK;
#pragma unroll
    for (int t = 0; t < KK; t++) { po[t] = bd[t]; io[t] = bi[t]; }
}

__global__ __launch_bounds__(128)
void knn_merge(const float* __restrict__ pd, const int* __restrict__ pi,
               int* __restrict__ idx_out) {
    const int g = blockIdx.x * 128 + threadIdx.x;
    float bd[KK]; int bi[KK];
#pragma unroll
    for (int t = 0; t < KK; t++) { bd[t] = FLT_MAX; bi[t] = 0; }
    const float* pp = pd + (size_t)g * SPLIT * KK;
    const int*   ii = pi + (size_t)g * SPLIT * KK;
    for (int c = 0; c < SPLIT * KK; c++) {
        float d = pp[c];
        if (d < bd[KK - 1]) insert16(bd, bi, d, ii[c]);
    }
#pragma unroll
    for (int t = 0; t < KK; t++) idx_out[(size_t)g * KK + t] = bi[t];
}

// ---------------------------------------------------------------------------
// k2: h[p][k*32+d] = BN(relu(rel @ w1 + b1)).  16 points/block, 256 thr.
// ---------------------------------------------------------------------------
__global__ __launch_bounds__(256)
void h_kernel(const float* __restrict__ xyz, const int* __restrict__ idx,
              const float* __restrict__ w1, const float* __restrict__ b1,
              const float* __restrict__ gamma1, const float* __restrict__ beta1,
              const float* __restrict__ mean1, const float* __restrict__ var1,
              float* __restrict__ H) {
    __shared__ float sw[96], sb[32], ssc[32], ssh[32];
    const int tid = threadIdx.x;
    if (tid < 96) sw[tid] = w1[tid];
    if (tid < 32) {
        sb[tid] = b1[tid];
        float sc = gamma1[tid] * rsqrtf(var1[tid] + BN_EPS);
        ssc[tid] = sc;
        ssh[tid] = beta1[tid] - mean1[tid] * sc;
    }
    __syncthreads();

    const int g0 = blockIdx.x * 16;
    const int p  = tid >> 4;
    const int k  = tid & 15;
    const int g  = g0 + p;
    const int b  = g >> 11;
    const int n  = g & (NN - 1);
    const int nbr = idx[(size_t)g * KK + k];

    const float* qp = xyz + ((size_t)b * NN + n) * 3;
    const float* np = xyz + ((size_t)b * NN + nbr) * 3;
    float qx = qp[0], qy = qp[1], qz = qp[2];
    float px = np[0], py = np[1], pz = np[2];
    float nm = (px != 0.0f || py != 0.0f || pz != 0.0f) ? 1.0f : 0.0f;
    float r0 = nm * (px - qx), r1 = nm * (py - qy), r2 = nm * (pz - qz);

    float* dst = H + (size_t)g * 512 + k * 32;
#pragma unroll
    for (int d4 = 0; d4 < 32; d4 += 4) {
        float4 o;
        float* ov = (float*)&o;
#pragma unroll
        for (int q = 0; q < 4; q++) {
            int d = d4 + q;
            float v = r0 * sw[d] + r1 * sw[32 + d] + r2 * sw[64 + d] + sb[d];
            v = fmaxf(v, 0.0f);
            ov[q] = v * ssc[d] + ssh[d];
        }
        *(float4*)(dst + d4) = o;
    }
}

// ---------------------------------------------------------------------------
// SGEMM: C[M x NMAT] = A[M x KMAT] @ B[KMAT x NMAT], 128x128 tile, 8x8 micro.
// EPI 0: C = acc + bias[n]           (k3: X = h@w2 + b2)
// EPI 1: C = relu(acc*sc+sh)*qmask   (k6: out)
// ---------------------------------------------------------------------------
#define BM 128
#define BNT 128
#define BKT 16

template<int NMAT, int KMAT, int EPI>
__global__ __launch_bounds__(256)
void sgemm(const float* __restrict__ A, const float* __restrict__ B,
           const float* __restrict__ e0, const float* __restrict__ e1,
           const float* __restrict__ e2, const float* __restrict__ e3,
           const float* __restrict__ xyz, float* __restrict__ C) {
    __shared__ float As[BKT][BM];
    __shared__ float Bs[BKT][BNT];
    __shared__ float smask[BM];
    __shared__ float ssc[BNT], ssh[BNT];

    const int tid  = threadIdx.x;
    const int row0 = blockIdx.x * BM;
    const int col0 = blockIdx.y * BNT;
    const int tx   = tid & 15;
    const int ty   = tid >> 4;

    if (EPI == 1) {
        if (tid < BM) {
            const float* p = xyz + (size_t)(row0 + tid) * 3;
            smask[tid] = (p[0] != 0.0f || p[1] != 0.0f || p[2] != 0.0f) ? 1.0f : 0.0f;
        }
        if (tid < NMAT) {
            float sc = e0[tid] * rsqrtf(e3[tid] + BN_EPS);   // gamma * rsqrt(var+eps)
            ssc[tid] = sc;
            ssh[tid] = e1[tid] - e2[tid] * sc;               // beta - mean*sc
        }
    }

    unsigned long long acc[8][4];
#pragma unroll
    for (int i = 0; i < 8; i++)
#pragma unroll
        for (int q = 0; q < 4; q++) acc[i][q] = 0ull;

    for (int k0 = 0; k0 < KMAT; k0 += BKT) {
        __syncthreads();
        // A tile 128x16 -> As[k][m]
        {
            int r = tid >> 2;
            int c = (tid & 3) * 4;
#pragma unroll
            for (int h2 = 0; h2 < 2; h2++) {
                float4 a = *(const float4*)(A + (size_t)(row0 + r + h2 * 64) * KMAT + k0 + c);
                As[c + 0][r + h2 * 64] = a.x;
                As[c + 1][r + h2 * 64] = a.y;
                As[c + 2][r + h2 * 64] = a.z;
                As[c + 3][r + h2 * 64] = a.w;
            }
        }
        // B tile 16x128 -> Bs[k][n]
        {
            int kr = tid >> 5;
            int cc = (tid & 31) * 4;
#pragma unroll
            for (int h2 = 0; h2 < 2; h2++) {
                *(float4*)&Bs[kr + h2 * 8][cc] =
                    *(const float4*)(B + (size_t)(k0 + kr + h2 * 8) * NMAT + col0 + cc);
            }
        }
        __syncthreads();

#pragma unroll
        for (int kk = 0; kk < BKT; kk++) {
            float a[8];
            *(float4*)&a[0] = *(const float4*)&As[kk][ty * 8];
            *(float4*)&a[4] = *(const float4*)&As[kk][ty * 8 + 4];
            ulonglong2 bA = *(const ulonglong2*)&Bs[kk][tx * 8];
            ulonglong2 bB = *(const ulonglong2*)&Bs[kk][tx * 8 + 4];
#pragma unroll
            for (int i = 0; i < 8; i++) {
                unsigned long long a2 = pack2(a[i], a[i]);
                ffma2(acc[i][0], a2, bA.x);
                ffma2(acc[i][1], a2, bA.y);
                ffma2(acc[i][2], a2, bB.x);
                ffma2(acc[i][3], a2, bB.y);
            }
        }
    }
    __syncthreads();

    // epilogue
    const int crow = row0 + ty * 8;
    const int ccol = col0 + tx * 8;
#pragma unroll
    for (int i = 0; i < 8; i++) {
        float v[8];
#pragma unroll
        for (int q = 0; q < 4; q++) {
            float2 p = unpack2(acc[i][q]);
            v[2 * q] = p.x; v[2 * q + 1] = p.y;
        }
        if (EPI == 0) {
#pragma unroll
            for (int q = 0; q < 8; q++) v[q] += e0[ccol - col0 + tx * 0 + (ccol + q) - ccol + col0 - col0 + (ccol + q) - ccol];  // placeholder
        }
        // (real epilogues below)
        float* cp = C + (size_t)(crow + i) * NMAT + ccol;
        if (EPI == 0) {
            // overwrite with correct bias add
#pragma unroll
            for (int q = 0; q < 8; q++) {
                float2 p = unpack2(acc[i][q >> 1]);
                v[q] = ((q & 1) ? p.y : p.x) + e0[ccol + q];
            }
        } else {
            float m = smask[ty * 8 + i];
#pragma unroll
            for (int q = 0; q < 8; q++) {
                int n = tx * 8 + q;
                v[q] = fmaxf(v[q] * ssc[n] + ssh[n], 0.0f) * m;
            }
        }
        *(float4*)cp       = make_float4(v[0], v[1], v[2], v[3]);
        *(float4*)(cp + 4) = make_float4(v[4], v[5], v[6], v[7]);
    }
}

// ---------------------------------------------------------------------------
// k4: lifted = relu(BN(gather(feat)@wl)) * nmask.
// GEMM M=262144(rows=p*16+k), N=64, K=64. BM=256 rows/block, 8x8 micro.
// ---------------------------------------------------------------------------
__global__ __launch_bounds__(256)
void lift_kernel(const float* __restrict__ feat, const int* __restrict__ idx,
                 const float* __restrict__ xyz, const float* __restrict__ wl,
                 const float* __restrict__ gamma_l, const float* __restrict__ beta_l,
                 const float* __restrict__ mean_l, const float* __restrict__ var_l,
                 float* __restrict__ L) {
    extern __shared__ float sm4[];
    float* As    = sm4;             // [64][256] transposed   16384
    float* Bs    = sm4 + 16384;     // [64][64]                4096
    float* smask = sm4 + 20480;     // [256]
    float* ssc   = sm4 + 20736;     // [64]
    float* ssh   = sm4 + 20800;     // [64]
    // total 20864 floats = 83456 B

    const int tid  = threadIdx.x;
    const int row0 = blockIdx.x * 256;

    {   // mask + BN consts
        int grow = row0 + tid;
        int nbr  = idx[grow];
        int b    = grow >> 15;
        const float* np = xyz + ((size_t)(b << 11) + nbr) * 3;
        smask[tid] = (np[0] != 0.0f || np[1] != 0.0f || np[2] != 0.0f) ? 1.0f : 0.0f;
        if (tid < 64) {
            float sc = gamma_l[tid] * rsqrtf(var_l[tid] + BN_EPS);
            ssc[tid] = sc;
            ssh[tid] = beta_l[tid] - mean_l[tid] * sc;
        }
    }
    // B tile: wl 64x64
    {
        int kr = tid >> 4;          // 0..15
        int cc = (tid & 15) * 4;
#pragma unroll
        for (int h2 = 0; h2 < 4; h2++)
            *(float4*)&Bs[(kr + h2 * 16) * 64 + cc] =
                *(const float4*)(wl + (size_t)(kr + h2 * 16) * 64 + cc);
    }
    // A tile: gathered features, transposed -> As[c][row]
    {
        int cc = (tid & 15) * 4;
#pragma unroll
        for (int h2 = 0; h2 < 16; h2++) {
            int r    = (tid >> 4) + h2 * 16;
            int grow = row0 + r;
            int nbr  = idx[grow];
            int b    = grow >> 15;
            float4 f = *(const float4*)(feat + ((size_t)(b << 11) + nbr) * 64 + cc);
            As[(cc + 0) * 256 + r] = f.x;
            As[(cc + 1) * 256 + r] = f.y;
            As[(cc + 2) * 256 + r] = f.z;
            As[(cc + 3) * 256 + r] = f.w;
        }
    }
    __syncthreads();

    const int tx = tid & 7;         // col group (8 cols each)
    const int ty = tid >> 3;        // row group (0..31, 8 rows each)
    unsigned long long acc[8][4];
#pragma unroll
    for (int i = 0; i < 8; i++)
#pragma unroll
        for (int q = 0; q < 4; q++) acc[i][q] = 0ull;

#pragma unroll 8
    for (int kk = 0; kk < 64; kk++) {
        float a[8];
        *(float4*)&a[0] = *(const float4*)&As[kk * 256 + ty * 8];
        *(float4*)&a[4] = *(const float4*)&As[kk * 256 + ty * 8 + 4];
        ulonglong2 bA = *(const ulonglong2*)&Bs[kk * 64 + tx * 8];
        ulonglong2 bB = *(const ulonglong2*)&Bs[kk * 64 + tx * 8 + 4];
#pragma unroll
        for (int i = 0; i < 8; i++) {
            unsigned long long a2 = pack2(a[i], a[i]);
            ffma2(acc[i][0], a2, bA.x);
            ffma2(acc[i][1], a2, bA.y);
            ffma2(acc[i][2], a2, bB.x);
            ffma2(acc[i][3], a2, bB.y);
        }
    }

#pragma unroll
    for (int i = 0; i < 8; i++) {
        int rloc = ty * 8 + i;
        int grow = row0 + rloc;
        float m  = smask[rloc];
        float v[8];
#pragma unroll
        for (int q = 0; q < 8; q++) {
            float2 p = unpack2(acc[i][q >> 1]);
            int n = tx * 8 + q;
            float x = ((q & 1) ? p.y : p.x) * ssc[n] + ssh[n];
            v[q] = fmaxf(x, 0.0f) * m;
        }
        float* cp = L + (size_t)grow * 64 + tx * 8;
        *(float4*)cp       = make_float4(v[0], v[1], v[2], v[3]);
        *(float4*)(cp + 4) = make_float4(v[4], v[5], v[6], v[7]);
    }
}

// ---------------------------------------------------------------------------
// k5: transformed[p][i][l] = sum_j X[p][i][j] * lifted[p][j][l].
// 16 points/block, thread = (p, i), acc[64] in regs.
// ---------------------------------------------------------------------------
__global__ __launch_bounds__(256)
void xform_kernel(const float* __restrict__ X, const float* __restrict__ L,
                  float* __restrict__ T) {
    extern __shared__ float sm5[];
    float* sX = sm5;            // 16*256  =  4096
    float* sL = sm5 + 4096;     // 16*1024 = 16384
    // total 20480 floats = 81920 B

    const int tid = threadIdx.x;
    const int g0  = blockIdx.x * 16;

    for (int e = tid * 4; e < 4096; e += 1024)
        *(float4*)&sX[e] = *(const float4*)(X + (size_t)g0 * 256 + e);
    for (int e = tid * 4; e < 16384; e += 1024)
        *(float4*)&sL[e] = *(const float4*)(L + (size_t)g0 * 1024 + e);
    __syncthreads();

    const int p = tid >> 4;
    const int i = tid & 15;

    float xr[16];
    {
        const float4* xp = (const float4*)&sX[p * 256 + i * 16];
#pragma unroll
        for (int q = 0; q < 4; q++) *(float4*)&xr[q * 4] = xp[q];
    }

    unsigned long long acc[32];
#pragma unroll
    for (int q = 0; q < 32; q++) acc[q] = 0ull;

#pragma unroll
    for (int j = 0; j < 16; j++) {
        unsigned long long xv = pack2(xr[j], xr[j]);
        const ulonglong2* lp = (const ulonglong2*)&sL[p * 1024 + j * 64];
#pragma unroll
        for (int q = 0; q < 16; q++) {
            ulonglong2 lv = lp[q];
            ffma2(acc[2 * q],     xv, lv.x);
            ffma2(acc[2 * q + 1], xv, lv.y);
        }
    }

    float* dst = T + (size_t)(g0 + p) * 1024 + i * 64;
#pragma unroll
    for (int q = 0; q < 16; q++) {
        float2 a = unpack2(acc[2 * q]);
        float2 b2v = unpack2(acc[2 * q + 1]);
        *(float4*)(dst + q * 4) = make_float4(a.x, a.y, b2v.x, b2v.y);
    }
}

// ---------------------------------------------------------------------------
extern "C" void kernel_launch(void* const* d_in, const int* in_sizes, int n_in,
                              void* d_out, int out_size) {
    const float* xyz     = (const float*)d_in[0];
    const float* feat    = (const float*)d_in[1];
    const float* w1      = (const float*)d_in[2];
    const float* b1      = (const float*)d_in[3];
    const float* gamma1  = (const float*)d_in[4];
    const float* beta1   = (const float*)d_in[5];
    const float* mean1   = (const float*)d_in[6];
    const float* var1    = (const float*)d_in[7];
    const float* w2      = (const float*)d_in[8];
    const float* b2      = (const float*)d_in[9];
    const float* wl      = (const float*)d_in[10];
    const float* gamma_l = (const float*)d_in[11];
    const float* beta_l  = (const float*)d_in[12];
    const float* mean_l  = (const float*)d_in[13];
    const float* var_l   = (const float*)d_in[14];
    const float* wf      = (const float*)d_in[15];
    const float* gamma_f = (const float*)d_in[16];
    const float* beta_f  = (const float*)d_in[17];
    const float* mean_f  = (const float*)d_in[18];
    const float* var_f   = (const float*)d_in[19];
    float* out = (float*)d_out;

    float *pd_ptr, *h_ptr, *X_ptr, *L_ptr, *T_ptr;
    int *pi_ptr, *idx_ptr;
    cudaGetSymbolAddress((void**)&pd_ptr, g_pd);
    cudaGetSymbolAddress((void**)&pi_ptr, g_pi);
    cudaGetSymbolAddress((void**)&idx_ptr, g_idx);
    cudaGetSymbolAddress((void**)&h_ptr, g_h);
    cudaGetSymbolAddress((void**)&X_ptr, g_X);
    cudaGetSymbolAddress((void**)&L_ptr, g_lift);
    cudaGetSymbolAddress((void**)&T_ptr, g_tr);

    knn_part<<<(NPTS / 128) * SPLIT, 128>>>(xyz, pd_ptr, pi_ptr);
    knn_merge<<<NPTS / 128, 128>>>(pd_ptr, pi_ptr, idx_ptr);

    h_kernel<<<NPTS / 16, 256>>>(xyz, idx_ptr, w1, b1, gamma1, beta1,
                                 mean1, var1, h_ptr);

    // k3: X = h @ w2 + b2   (M=16384, N=256, K=512)
    sgemm<256, 512, 0><<<dim3(NPTS / BM, 2), 256>>>(
        h_ptr, w2, b2, nullptr, nullptr, nullptr, xyz, X_ptr);

    // k4: lifted
    cudaFuncSetAttribute(lift_kernel,
                         cudaFuncAttributeMaxDynamicSharedMemorySize, 83456);
    lift_kernel<<<NPTS * 16 / 256, 256, 83456>>>(
        feat, idx_ptr, xyz, wl, gamma_l, beta_l, mean_l, var_l, L_ptr);

    // k5: transformed
    cudaFuncSetAttribute(xform_kernel,
                         cudaFuncAttributeMaxDynamicSharedMemorySize, 81920);
    xform_kernel<<<NPTS / 16, 256, 81920>>>(X_ptr, L_ptr, T_ptr);

    // k6: out = relu(BN(tr @ wf)) * qmask   (M=16384, N=128, K=1024)
    sgemm<128, 1024, 1><<<dim3(NPTS / BM, 1), 256>>>(
        T_ptr, wf, gamma_f, beta_f, mean_f, var_f, xyz, out);
}